// round 4
// baseline (speedup 1.0000x reference)
#include <cuda_runtime.h>
#include <cstdint>

#define EPS      1e-6f
#define IMG_H    512
#define IMG_W    512
#define PLANES   64            // B*C = 4*16
#define PX       4             // pixels per thread in x
#define TX       (IMG_W / PX)  // 128 threads
#define ROWS_OUT 8             // output rows per thread

#define EXPM     0.60653065971263342f   // exp(-0.5), theta=1
#define EXPM_9   (EXPM / 9.0f)
#define EPS_EXPM (EPS * EXPM)

typedef unsigned long long u64;

__device__ __forceinline__ u64 pk2(float lo, float hi) {
    u64 r; asm("mov.b64 %0,{%1,%2};" : "=l"(r) : "f"(lo), "f"(hi)); return r;
}
__device__ __forceinline__ void upk2(float& lo, float& hi, u64 v) {
    asm("mov.b64 {%0,%1},%2;" : "=f"(lo), "=f"(hi) : "l"(v));
}
__device__ __forceinline__ u64 add2(u64 a, u64 b) {
    u64 r; asm("add.rn.f32x2 %0,%1,%2;" : "=l"(r) : "l"(a), "l"(b)); return r;
}

__device__ __forceinline__ float fsqrt_approx(float a) {
    float r; asm("sqrt.approx.f32 %0, %1;" : "=f"(r) : "f"(a)); return r;
}
__device__ __forceinline__ float frcp_approx(float a) {
    float r; asm("rcp.approx.f32 %0, %1;" : "=f"(r) : "f"(a)); return r;
}

struct PRow { float4 m; float lf, rt; };

// Prefetch: vector load + lane-edge halo scalars only (predicated, 1 active lane).
__device__ __forceinline__ PRow pref(const float* __restrict__ row, int x0,
                                     int lane, bool valid) {
    PRow r;
    if (valid) {
        r.m  = *reinterpret_cast<const float4*>(row + x0);
        r.lf = (lane == 0  && x0 > 0)          ? __ldg(row + x0 - 1)  : 0.0f;
        r.rt = (lane == 31 && x0 + PX < IMG_W) ? __ldg(row + x0 + PX) : 0.0f;
    } else {
        r.m = make_float4(0.f, 0.f, 0.f, 0.f); r.lf = 0.f; r.rt = 0.f;
    }
    return r;
}

// Consume: interior halos come from neighbor lanes via shuffle.
__device__ __forceinline__ void consume(const PRow& R, int lane, float v[6]) {
    v[1] = R.m.x; v[2] = R.m.y; v[3] = R.m.z; v[4] = R.m.w;
    const float l  = __shfl_up_sync(0xffffffffu, R.m.w, 1);
    const float rr = __shfl_down_sync(0xffffffffu, R.m.x, 1);
    v[0] = (lane == 0)  ? R.lf : l;
    v[5] = (lane == 31) ? R.rt : rr;
}

// Per-row horizontal triple sums (S1/S2/Sp contributions), packed as px-pairs.
__device__ __forceinline__ void rowstats(const float v[6],
                                         u64 H1[2], u64 H2[2], u64 HP[2]) {
    float p[6];
#pragma unroll
    for (int j = 0; j < 6; ++j) p[j] = v[j] * __logf(v[j] + EPS);
    float h1[4], h2[4], hp[4];
#pragma unroll
    for (int i = 0; i < 4; ++i) {
        h1[i] = v[i] + v[i + 1] + v[i + 2];
        h2[i] = fmaf(v[i], v[i], fmaf(v[i + 1], v[i + 1], v[i + 2] * v[i + 2]));
        hp[i] = p[i] + p[i + 1] + p[i + 2];
    }
    H1[0] = pk2(h1[0], h1[1]); H1[1] = pk2(h1[2], h1[3]);
    H2[0] = pk2(h2[0], h2[1]); H2[1] = pk2(h2[2], h2[3]);
    HP[0] = pk2(hp[0], hp[1]); HP[1] = pk2(hp[2], hp[3]);
}

__global__ __launch_bounds__(TX, 6)
void texture_martingale_kernel(const float* __restrict__ x,
                               float* __restrict__ out) {
    const int plane = blockIdx.y;                   // 0..63 (b*16+c)
    const int y0    = blockIdx.x * ROWS_OUT;
    const int x0    = threadIdx.x * PX;
    const int lane  = threadIdx.x & 31;

    const float* __restrict__ in = x + (size_t)plane * (IMG_H * IMG_W);

    float v[3][6];
    u64 H1[3][2], H2[3][2], HP[3][2];

    // Prologue: rows y0-1, y0 into ring slots 0,1; prefetch y0+1.
    {
        PRow r0 = pref(in + (y0 - 1) * IMG_W, x0, lane, y0 > 0);
        PRow r1 = pref(in +  y0      * IMG_W, x0, lane, true);
        consume(r0, lane, v[0]); rowstats(v[0], H1[0], H2[0], HP[0]);
        consume(r1, lane, v[1]); rowstats(v[1], H1[1], H2[1], HP[1]);
    }
    PRow nx = pref(in + (y0 + 1) * IMG_W, x0, lane, true);  // y0+1 <= 505 valid

    const size_t planeSz = (size_t)IMG_H * IMG_W;
    float* __restrict__ o0 = out + (size_t)(4 * plane) * planeSz
                                 + (size_t)y0 * IMG_W + x0;
    float* __restrict__ o1 = o0 + planeSz;
    float* __restrict__ o2 = o0 + 2 * planeSz;
    float* __restrict__ o3 = o0 + 3 * planeSz;

#pragma unroll
    for (int r = 0; r < ROWS_OUT; ++r) {
        const int sa = r % 3, sb = (r + 1) % 3, sc = (r + 2) % 3;

        // Commit prefetched row, then immediately issue next row's loads.
        consume(nx, lane, v[sc]);
        const int yy = y0 + r + 2;
        nx = pref(in + yy * IMG_W, x0, lane, yy < IMG_H);

        rowstats(v[sc], H1[sc], H2[sc], HP[sc]);

        // Vertical sums over 3 rows, packed px-pairs.
        float S1[4], S2[4], Sp[4];
#pragma unroll
        for (int k = 0; k < 2; ++k) {
            const u64 s1 = add2(add2(H1[sa][k], H1[sb][k]), H1[sc][k]);
            const u64 s2 = add2(add2(H2[sa][k], H2[sb][k]), H2[sc][k]);
            const u64 sp = add2(add2(HP[sa][k], HP[sb][k]), HP[sc][k]);
            upk2(S1[2 * k], S1[2 * k + 1], s1);
            upk2(S2[2 * k], S2[2 * k + 1], s2);
            upk2(Sp[2 * k], Sp[2 * k + 1], sp);
        }

        float oc[PX], oe[PX], ot[PX], oh[PX];
#pragma unroll
        for (int i = 0; i < PX; ++i) {
            const float mean = S1[i] * (1.0f / 9.0f);
            const float vnum = fmaxf(fmaf(-S1[i], mean, S2[i]), 0.0f);
            const float sd   = fsqrt_approx(vnum * 0.125f) + EPS;
            const float rden = frcp_approx(sd * sd);

            float sab = 0.0f;
#pragma unroll
            for (int jj = 0; jj < 3; ++jj) {
                sab += fabsf(v[sa][i + jj] - mean);
                sab += fabsf(v[sb][i + jj] - mean);
                sab += fabsf(v[sc][i + jj] - mean);
            }
            const float hom = frcp_approx(fmaf(sab, 1.0f / 9.0f, 1.0f));

            oc[i] = fmaf(vnum * EXPM_9, rden, EPS_EXPM);   // contrast
            oe[i] = fmaf(S2[i],  EXPM_9,  EPS_EXPM);       // energy
            ot[i] = fmaf(Sp[i], -EXPM_9,  EPS_EXPM);       // entropy
            oh[i] = fmaf(hom, EXPM,       EPS_EXPM);       // homogeneity
        }

        *reinterpret_cast<float4*>(o0) = make_float4(oc[0], oc[1], oc[2], oc[3]);
        *reinterpret_cast<float4*>(o1) = make_float4(oe[0], oe[1], oe[2], oe[3]);
        *reinterpret_cast<float4*>(o2) = make_float4(ot[0], ot[1], ot[2], ot[3]);
        *reinterpret_cast<float4*>(o3) = make_float4(oh[0], oh[1], oh[2], oh[3]);
        o0 += IMG_W; o1 += IMG_W; o2 += IMG_W; o3 += IMG_W;
    }
}

extern "C" void kernel_launch(void* const* d_in, const int* in_sizes, int n_in,
                              void* d_out, int out_size) {
    const float* x = (const float*)d_in[0];
    float* out = (float*)d_out;

    dim3 block(TX, 1);
    dim3 grid(IMG_H / ROWS_OUT, PLANES);
    texture_martingale_kernel<<<grid, block>>>(x, out);
}